// round 1
// baseline (speedup 1.0000x reference)
#include <cuda_runtime.h>
#include <math.h>

#define B 16
#define T 2048
#define D 768
#define A 5
#define NSEG1 8     // t-segments for mean partials
#define NSEG3 16    // t-segments for agent_v partials (128 t each)

// ---- scratch (device globals; no allocation) ----
__device__ float g_mpart[B][NSEG1][D];        // 384 KB
__device__ float g_m[B][D];                   // 48 KB
__device__ float g_s[B][T];                   // 128 KB
__device__ float g_w[B][A][T];                // 640 KB
__device__ float g_avpart[B][NSEG3][A][D];    // 3.75 MB
__device__ float g_av[B][A][D];               // 240 KB
__device__ float g_p[T][A];                   // 40 KB

// ---------------------------------------------------------------
// Kernel 1: masked-sum partials of q over t-segments.
// grid (NSEG1, D/256, B), block 256. Reads q once (100MB).
__global__ void k_mean_part(const float* __restrict__ q,
                            const int* __restrict__ mask) {
    const int seg = blockIdx.x, dc = blockIdx.y, b = blockIdx.z;
    const int d = dc * 256 + threadIdx.x;
    const int t0 = seg * (T / NSEG1);
    const float* qb = q + (size_t)b * T * D + (size_t)t0 * D + d;
    const int* mb = mask + b * T + t0;
    float acc = 0.f;
    #pragma unroll 4
    for (int tt = 0; tt < T / NSEG1; ++tt) {
        float val = qb[(size_t)tt * D];
        if (mb[tt]) acc += val;
    }
    g_mpart[b][seg][d] = acc;
}

// Kernel 1b: finish mean (divide by T, per torch semantics).
__global__ void k_mean_fin() {
    int i = blockIdx.x * 256 + threadIdx.x;   // B*D = 12288
    int b = i / D, d = i % D;
    float acc = 0.f;
    #pragma unroll
    for (int s = 0; s < NSEG1; ++s) acc += g_mpart[b][s][d];
    g_m[b][d] = acc * (1.0f / (float)T);
}

// ---------------------------------------------------------------
// Kernel 2: s[b,t] = k[b,t,:] . m[b,:]. One warp per t, 8 t per block.
// grid (T/8, B), block 256. Reads k once (100MB).
__global__ void k_skt(const float* __restrict__ k) {
    const int b = blockIdx.y;
    const int warp = threadIdx.x >> 5;
    const int lane = threadIdx.x & 31;
    const int t = blockIdx.x * 8 + warp;
    __shared__ float sm[D];
    for (int i = threadIdx.x; i < D; i += 256) sm[i] = g_m[b][i];
    __syncthreads();
    const float4* kr = (const float4*)(k + ((size_t)b * T + t) * D);
    const float4* mr = (const float4*)sm;
    float acc = 0.f;
    #pragma unroll
    for (int i = lane; i < D / 4; i += 32) {
        float4 kv = kr[i], mv = mr[i];
        acc += kv.x * mv.x + kv.y * mv.y + kv.z * mv.z + kv.w * mv.w;
    }
    #pragma unroll
    for (int o = 16; o; o >>= 1) acc += __shfl_down_sync(0xffffffffu, acc, o);
    if (lane == 0) g_s[b][t] = acc;
}

// ---------------------------------------------------------------
// Kernel 3a: w[b,a,t] = softmax_t(s[b,t] + b1[a,t]). grid (A, B), block 256.
__global__ void k_softmax_w(const float* __restrict__ b1) {
    const int a = blockIdx.x, b = blockIdx.y;
    const int tid = threadIdx.x;
    __shared__ float red[256];
    float vals[T / 256];
    float mx = -1e30f;
    #pragma unroll
    for (int i = 0; i < T / 256; ++i) {
        int t = tid + i * 256;
        float v = g_s[b][t] + b1[a * T + t];
        vals[i] = v;
        mx = fmaxf(mx, v);
    }
    red[tid] = mx; __syncthreads();
    for (int s = 128; s; s >>= 1) {
        if (tid < s) red[tid] = fmaxf(red[tid], red[tid + s]);
        __syncthreads();
    }
    mx = red[0]; __syncthreads();
    float sum = 0.f;
    #pragma unroll
    for (int i = 0; i < T / 256; ++i) {
        vals[i] = expf(vals[i] - mx);
        sum += vals[i];
    }
    red[tid] = sum; __syncthreads();
    for (int s = 128; s; s >>= 1) {
        if (tid < s) red[tid] += red[tid + s];
        __syncthreads();
    }
    float inv = 1.0f / red[0];
    #pragma unroll
    for (int i = 0; i < T / 256; ++i)
        g_w[b][a][tid + i * 256] = vals[i] * inv;
}

// ---------------------------------------------------------------
// Kernel 3b: agent_v partials. grid (NSEG3, D/256, B), block 256.
// Reads v exactly once (100MB); 5 accumulators per thread; w tile in smem.
__global__ void k_av_part(const float* __restrict__ v) {
    const int seg = blockIdx.x, dc = blockIdx.y, b = blockIdx.z;
    const int d = dc * 256 + threadIdx.x;
    const int TSEG = T / NSEG3;                 // 128
    const int t0 = seg * TSEG;
    __shared__ float sw[A][TSEG];
    for (int i = threadIdx.x; i < A * TSEG; i += 256)
        sw[i / TSEG][i % TSEG] = g_w[b][i / TSEG][t0 + i % TSEG];
    __syncthreads();
    const float* vb = v + ((size_t)b * T + t0) * D + d;
    float acc0 = 0.f, acc1 = 0.f, acc2 = 0.f, acc3 = 0.f, acc4 = 0.f;
    #pragma unroll 4
    for (int tt = 0; tt < TSEG; ++tt) {
        float vv = vb[(size_t)tt * D];
        acc0 += sw[0][tt] * vv;
        acc1 += sw[1][tt] * vv;
        acc2 += sw[2][tt] * vv;
        acc3 += sw[3][tt] * vv;
        acc4 += sw[4][tt] * vv;
    }
    g_avpart[b][seg][0][d] = acc0;
    g_avpart[b][seg][1][d] = acc1;
    g_avpart[b][seg][2][d] = acc2;
    g_avpart[b][seg][3][d] = acc3;
    g_avpart[b][seg][4][d] = acc4;
}

// Kernel 3c: reduce agent_v partials. B*A*D = 61440 threads.
__global__ void k_av_fin() {
    int i = blockIdx.x * 256 + threadIdx.x;
    int b = i / (A * D);
    int r = i % (A * D);
    int a = r / D, d = r % D;
    float acc = 0.f;
    #pragma unroll
    for (int s = 0; s < NSEG3; ++s) acc += g_avpart[b][s][a][d];
    g_av[b][a][d] = acc;
}

// ---------------------------------------------------------------
// Kernel 4a: p[t,a] = softmax_a(b2[t,:]). (stage-2 softmax is q-independent
// by shift invariance: logits = q.m (const in a) + b2.)
__global__ void k_softmax_p(const float* __restrict__ b2) {
    int t = blockIdx.x * 256 + threadIdx.x;   // exactly T threads
    float v[A];
    float mx = -1e30f;
    #pragma unroll
    for (int a = 0; a < A; ++a) { v[a] = b2[t * A + a]; mx = fmaxf(mx, v[a]); }
    float sum = 0.f;
    #pragma unroll
    for (int a = 0; a < A; ++a) { v[a] = expf(v[a] - mx); sum += v[a]; }
    float inv = 1.0f / sum;
    #pragma unroll
    for (int a = 0; a < A; ++a) g_p[t][a] = v[a] * inv;
}

// Kernel 4b: x[b,t,d] = sum_a p[t,a] * agent_v[b,a,d].
// grid (T/16, D/256, B), block 256. Writes x once (100MB).
__global__ void k_epilogue(float* __restrict__ out) {
    const int tb = blockIdx.x, dc = blockIdx.y, b = blockIdx.z;
    const int d = dc * 256 + threadIdx.x;
    const int t0 = tb * 16;
    __shared__ float sp[16][A];
    if (threadIdx.x < 16 * A)
        sp[threadIdx.x / A][threadIdx.x % A] = g_p[t0 + threadIdx.x / A][threadIdx.x % A];
    float av0 = g_av[b][0][d], av1 = g_av[b][1][d], av2 = g_av[b][2][d],
          av3 = g_av[b][3][d], av4 = g_av[b][4][d];
    __syncthreads();
    float* ob = out + ((size_t)b * T + t0) * D + d;
    #pragma unroll
    for (int tt = 0; tt < 16; ++tt) {
        float r = sp[tt][0] * av0 + sp[tt][1] * av1 + sp[tt][2] * av2 +
                  sp[tt][3] * av3 + sp[tt][4] * av4;
        ob[(size_t)tt * D] = r;
    }
}

// ---------------------------------------------------------------
extern "C" void kernel_launch(void* const* d_in, const int* in_sizes, int n_in,
                              void* d_out, int out_size) {
    const float* qkv  = (const float*)d_in[0];        // [3,B,T,D]
    const int*   mask = (const int*)d_in[1];          // [B,T]
    const float* b1   = (const float*)d_in[2];        // [A,T]
    const float* b2   = (const float*)d_in[3];        // [T,A]
    float* out = (float*)d_out;                       // [B,T,D]

    const float* q = qkv;
    const float* k = qkv + (size_t)B * T * D;
    const float* v = qkv + 2 * (size_t)B * T * D;

    k_mean_part<<<dim3(NSEG1, D / 256, B), 256>>>(q, mask);
    k_mean_fin<<<(B * D) / 256, 256>>>();
    k_skt<<<dim3(T / 8, B), 256>>>(k);
    k_softmax_w<<<dim3(A, B), 256>>>(b1);
    k_av_part<<<dim3(NSEG3, D / 256, B), 256>>>(v);
    k_av_fin<<<(B * A * D) / 256, 256>>>();
    k_softmax_p<<<T / 256, 256>>>(b2);
    k_epilogue<<<dim3(T / 16, D / 256, B), 256>>>(out);
}

// round 2
// speedup vs baseline: 1.3166x; 1.3166x over previous
#include <cuda_runtime.h>
#include <math.h>

#define B 16
#define T 2048
#define D 768
#define D4 192          // D/4 float4 lanes
#define A 5
#define NSEG1 32        // t-segments for mean partials (64 t each)
#define NSEG3 32        // t-segments for agent_v partials (64 t each)

// ---- scratch (device globals; no allocation) ----
__device__ float4 g_mpart[B][NSEG1][D4];       // 1.5 MB
__device__ float4 g_m[B][D4];                  // 48 KB
__device__ float  g_s[B][T];                   // 128 KB
__device__ float  g_w[B][A][T];                // 640 KB
__device__ float4 g_avpart[B][NSEG3][A][D4];   // 7.9 MB
__device__ float4 g_av[B][A][D4];              // 240 KB

// ---------------------------------------------------------------
// Kernel 1: masked-sum partials of q. grid (NSEG1, B), block 192 (one float4/d).
// Reads q exactly once (100MB), fully coalesced 16B/thread loads.
__global__ void k_mean_part(const float4* __restrict__ q,
                            const int* __restrict__ mask) {
    const int seg = blockIdx.x, b = blockIdx.y;
    const int tid = threadIdx.x;               // 0..191 == d4 lane
    const int TSEG = T / NSEG1;                // 64
    const int t0 = seg * TSEG;
    __shared__ float sm_mf[T / NSEG1];
    if (tid < TSEG) sm_mf[tid] = (float)mask[b * T + t0 + tid];
    __syncthreads();
    const float4* qb = q + ((size_t)b * T + t0) * D4 + tid;
    float4 acc = make_float4(0.f, 0.f, 0.f, 0.f);
    #pragma unroll 8
    for (int tt = 0; tt < TSEG; ++tt) {
        float4 v = qb[(size_t)tt * D4];
        float mf = sm_mf[tt];
        acc.x += mf * v.x; acc.y += mf * v.y;
        acc.z += mf * v.z; acc.w += mf * v.w;
    }
    g_mpart[b][seg][tid] = acc;
}

// Kernel 1b: finish mean. B*D4 = 3072 threads.
__global__ void k_mean_fin() {
    int i = blockIdx.x * 256 + threadIdx.x;
    if (i >= B * D4) return;
    int b = i / D4, d = i % D4;
    float4 acc = make_float4(0.f, 0.f, 0.f, 0.f);
    #pragma unroll
    for (int s = 0; s < NSEG1; ++s) {
        float4 v = g_mpart[b][s][d];
        acc.x += v.x; acc.y += v.y; acc.z += v.z; acc.w += v.w;
    }
    const float inv = 1.0f / (float)T;
    acc.x *= inv; acc.y *= inv; acc.z *= inv; acc.w *= inv;
    g_m[b][d] = acc;
}

// ---------------------------------------------------------------
// Kernel 2: s[b,t] = k[b,t,:] . m[b,:]. One warp per t, 8 t per block.
// grid (T/8, B), block 256. Reads k once (100MB), float4, fully unrolled.
__global__ void k_skt(const float4* __restrict__ k) {
    const int b = blockIdx.y;
    const int warp = threadIdx.x >> 5;
    const int lane = threadIdx.x & 31;
    const int t = blockIdx.x * 8 + warp;
    __shared__ float4 sm[D4];
    if (threadIdx.x < D4) sm[threadIdx.x] = g_m[b][threadIdx.x];
    __syncthreads();
    const float4* kr = k + ((size_t)b * T + t) * D4;
    float acc = 0.f;
    #pragma unroll
    for (int i = 0; i < D4 / 32; ++i) {      // 6 iterations, MLP 6x16B
        float4 kv = kr[lane + i * 32];
        float4 mv = sm[lane + i * 32];
        acc += kv.x * mv.x + kv.y * mv.y + kv.z * mv.z + kv.w * mv.w;
    }
    #pragma unroll
    for (int o = 16; o; o >>= 1) acc += __shfl_down_sync(0xffffffffu, acc, o);
    if (lane == 0) g_s[b][t] = acc;
}

// ---------------------------------------------------------------
// Kernel 3a: w[b,a,t] = softmax_t(s[b,t] + b1[a,t]). grid (A*B), block 512.
// Warp-shuffle reductions, single smem round per reduction.
__global__ void k_softmax_w(const float* __restrict__ b1) {
    const int a = blockIdx.x % A, b = blockIdx.x / A;
    const int tid = threadIdx.x;
    const int lane = tid & 31, warp = tid >> 5;   // 16 warps
    __shared__ float red[16];
    float vals[T / 512];
    float mx = -1e30f;
    #pragma unroll
    for (int i = 0; i < T / 512; ++i) {
        int t = tid + i * 512;
        float v = g_s[b][t] + b1[a * T + t];
        vals[i] = v;
        mx = fmaxf(mx, v);
    }
    #pragma unroll
    for (int o = 16; o; o >>= 1) mx = fmaxf(mx, __shfl_xor_sync(0xffffffffu, mx, o));
    if (lane == 0) red[warp] = mx;
    __syncthreads();
    float m2 = red[lane & 15];
    #pragma unroll
    for (int o = 8; o; o >>= 1) m2 = fmaxf(m2, __shfl_xor_sync(0xffffffffu, m2, o));
    mx = m2;
    float sum = 0.f;
    #pragma unroll
    for (int i = 0; i < T / 512; ++i) {
        vals[i] = expf(vals[i] - mx);
        sum += vals[i];
    }
    #pragma unroll
    for (int o = 16; o; o >>= 1) sum += __shfl_xor_sync(0xffffffffu, sum, o);
    __syncthreads();
    if (lane == 0) red[warp] = sum;
    __syncthreads();
    float s2 = red[lane & 15];
    #pragma unroll
    for (int o = 8; o; o >>= 1) s2 += __shfl_xor_sync(0xffffffffu, s2, o);
    float inv = 1.0f / s2;
    #pragma unroll
    for (int i = 0; i < T / 512; ++i)
        g_w[b][a][tid + i * 512] = vals[i] * inv;
}

// ---------------------------------------------------------------
// Kernel 3b: agent_v partials. grid (NSEG3, B), block 192 (one float4/d).
// Reads v exactly once (100MB); 5 float4 accumulators; w tile in smem.
__global__ void k_av_part(const float4* __restrict__ v) {
    const int seg = blockIdx.x, b = blockIdx.y;
    const int tid = threadIdx.x;
    const int TSEG = T / NSEG3;                 // 64
    const int t0 = seg * TSEG;
    __shared__ float sw[A][T / NSEG3];
    for (int i = tid; i < A * TSEG; i += 192)
        sw[i / TSEG][i % TSEG] = g_w[b][i / TSEG][t0 + i % TSEG];
    __syncthreads();
    const float4* vb = v + ((size_t)b * T + t0) * D4 + tid;
    float4 a0 = make_float4(0,0,0,0), a1 = a0, a2 = a0, a3 = a0, a4 = a0;
    #pragma unroll 4
    for (int tt = 0; tt < TSEG; ++tt) {
        float4 vv = vb[(size_t)tt * D4];
        float w0 = sw[0][tt], w1 = sw[1][tt], w2 = sw[2][tt],
              w3 = sw[3][tt], w4 = sw[4][tt];
        a0.x += w0*vv.x; a0.y += w0*vv.y; a0.z += w0*vv.z; a0.w += w0*vv.w;
        a1.x += w1*vv.x; a1.y += w1*vv.y; a1.z += w1*vv.z; a1.w += w1*vv.w;
        a2.x += w2*vv.x; a2.y += w2*vv.y; a2.z += w2*vv.z; a2.w += w2*vv.w;
        a3.x += w3*vv.x; a3.y += w3*vv.y; a3.z += w3*vv.z; a3.w += w3*vv.w;
        a4.x += w4*vv.x; a4.y += w4*vv.y; a4.z += w4*vv.z; a4.w += w4*vv.w;
    }
    g_avpart[b][seg][0][tid] = a0;
    g_avpart[b][seg][1][tid] = a1;
    g_avpart[b][seg][2][tid] = a2;
    g_avpart[b][seg][3][tid] = a3;
    g_avpart[b][seg][4][tid] = a4;
}

// Kernel 3c: reduce agent_v partials. B*A*D4 = 15360 threads.
__global__ void k_av_fin() {
    int i = blockIdx.x * 256 + threadIdx.x;
    if (i >= B * A * D4) return;
    int b = i / (A * D4);
    int r = i % (A * D4);
    int a = r / D4, d = r % D4;
    float4 acc = make_float4(0.f, 0.f, 0.f, 0.f);
    #pragma unroll
    for (int s = 0; s < NSEG3; ++s) {
        float4 v = g_avpart[b][s][a][d];
        acc.x += v.x; acc.y += v.y; acc.z += v.z; acc.w += v.w;
    }
    g_av[b][a][d] = acc;
}

// ---------------------------------------------------------------
// Kernel 4: epilogue with inline stage-2 softmax.
// x[b,t,d] = sum_a softmax_a(b2[t,:])[a] * agent_v[b,a,d]
// (stage-2 softmax is q-independent by shift invariance: logits = q.m + b2,
//  and q.m is constant along a.)
// grid (T/32, B), block 192 (one float4/d). Writes x once (100MB).
__global__ void k_epilogue(const float* __restrict__ b2,
                           float4* __restrict__ out) {
    const int tb = blockIdx.x, b = blockIdx.y;
    const int tid = threadIdx.x;
    const int t0 = tb * 32;
    __shared__ float sp[32][A];
    if (tid < 32) {
        int t = t0 + tid;
        float v[A];
        float mx = -1e30f;
        #pragma unroll
        for (int a = 0; a < A; ++a) { v[a] = b2[t * A + a]; mx = fmaxf(mx, v[a]); }
        float sum = 0.f;
        #pragma unroll
        for (int a = 0; a < A; ++a) { v[a] = expf(v[a] - mx); sum += v[a]; }
        float inv = 1.0f / sum;
        #pragma unroll
        for (int a = 0; a < A; ++a) sp[tid][a] = v[a] * inv;
    }
    float4 av0 = g_av[b][0][tid], av1 = g_av[b][1][tid], av2 = g_av[b][2][tid],
           av3 = g_av[b][3][tid], av4 = g_av[b][4][tid];
    __syncthreads();
    float4* ob = out + ((size_t)b * T + t0) * D4 + tid;
    #pragma unroll 4
    for (int tt = 0; tt < 32; ++tt) {
        float p0 = sp[tt][0], p1 = sp[tt][1], p2 = sp[tt][2],
              p3 = sp[tt][3], p4 = sp[tt][4];
        float4 r;
        r.x = p0*av0.x + p1*av1.x + p2*av2.x + p3*av3.x + p4*av4.x;
        r.y = p0*av0.y + p1*av1.y + p2*av2.y + p3*av3.y + p4*av4.y;
        r.z = p0*av0.z + p1*av1.z + p2*av2.z + p3*av3.z + p4*av4.z;
        r.w = p0*av0.w + p1*av1.w + p2*av2.w + p3*av3.w + p4*av4.w;
        ob[(size_t)tt * D4] = r;
    }
}

// ---------------------------------------------------------------
extern "C" void kernel_launch(void* const* d_in, const int* in_sizes, int n_in,
                              void* d_out, int out_size) {
    const float* qkv  = (const float*)d_in[0];        // [3,B,T,D]
    const int*   mask = (const int*)d_in[1];          // [B,T]
    const float* b1   = (const float*)d_in[2];        // [A,T]
    const float* b2   = (const float*)d_in[3];        // [T,A]
    float* out = (float*)d_out;                       // [B,T,D]

    const float4* q = (const float4*)qkv;
    const float4* k = (const float4*)(qkv + (size_t)B * T * D);
    const float4* v = (const float4*)(qkv + 2 * (size_t)B * T * D);

    k_mean_part<<<dim3(NSEG1, B), 192>>>(q, mask);
    k_mean_fin<<<(B * D4 + 255) / 256, 256>>>();
    k_skt<<<dim3(T / 8, B), 256>>>(k);
    k_softmax_w<<<A * B, 512>>>(b1);
    k_av_part<<<dim3(NSEG3, B), 192>>>(v);
    k_av_fin<<<(B * A * D4 + 255) / 256, 256>>>();
    k_epilogue<<<dim3(T / 32, B), 192>>>(b2, (float4*)out);
}